// round 1
// baseline (speedup 1.0000x reference)
#include <cuda_runtime.h>
#include <cuda_bf16.h>

// BlockConvolutionLean: out = segmented-exclusive-cumsum_8( A @ W^T ) + b_eff
// A = seq_vector [M=N*S, K=256] fp32, W [T=256, K=256] fp32, bias[8].
// b_eff[i] = bias[i], except b_eff[0] = 2*bias[0].
//
// Classic 128x128x16 SGEMM with 8x8 register micro-tiles. Thread (ty,tx)
// owns rows ty*8..ty*8+7 — exactly one aligned 8-token block, so the
// blockwise exclusive scan is done entirely in registers in the epilogue.

#define BM 128
#define BN 128
#define BK 16
#define TM 8
#define TN 8
#define THREADS 256

__global__ __launch_bounds__(THREADS, 2)
void block_conv_sgemm_kernel(const float* __restrict__ A,     // [M, K]
                             const float* __restrict__ W,     // [T, K]
                             const float* __restrict__ bias,  // [8]
                             float* __restrict__ out,         // [M, T]
                             int M, int K, int T)
{
    __shared__ float As[BK][BM];   // stored k-major for broadcast-friendly LDS
    __shared__ float Bs[BK][BN];

    const int tid = threadIdx.x;
    const int tx = tid & 15;   // 16 col-groups
    const int ty = tid >> 4;   // 16 row-groups (each = one 8-token block)
    const int blockRow = blockIdx.y * BM;
    const int blockCol = blockIdx.x * BN;

    float acc[TM][TN];
#pragma unroll
    for (int i = 0; i < TM; i++)
#pragma unroll
        for (int j = 0; j < TN; j++) acc[i][j] = 0.f;

    const int numK = K / BK;   // 16
    for (int kt = 0; kt < numK; kt++) {
        const int k0 = kt * BK;

        // Load A and B tiles: 128 rows x 16 cols each = 512 float4 per tile,
        // 2 float4 per thread per tile. Transpose into [k][row] layout.
#pragma unroll
        for (int l = 0; l < 2; l++) {
            int v   = tid + l * THREADS;
            int row = v >> 2;            // 0..127
            int c4  = (v & 3) << 2;      // 0,4,8,12

            float4 av = *reinterpret_cast<const float4*>(
                &A[(blockRow + row) * K + k0 + c4]);
            As[c4 + 0][row] = av.x;
            As[c4 + 1][row] = av.y;
            As[c4 + 2][row] = av.z;
            As[c4 + 3][row] = av.w;

            float4 bv = *reinterpret_cast<const float4*>(
                &W[(blockCol + row) * K + k0 + c4]);
            Bs[c4 + 0][row] = bv.x;
            Bs[c4 + 1][row] = bv.y;
            Bs[c4 + 2][row] = bv.z;
            Bs[c4 + 3][row] = bv.w;
        }
        __syncthreads();

#pragma unroll
        for (int kk = 0; kk < BK; kk++) {
            float a[TM], b[TN];
            *reinterpret_cast<float4*>(&a[0]) =
                *reinterpret_cast<const float4*>(&As[kk][ty * TM]);
            *reinterpret_cast<float4*>(&a[4]) =
                *reinterpret_cast<const float4*>(&As[kk][ty * TM + 4]);
            *reinterpret_cast<float4*>(&b[0]) =
                *reinterpret_cast<const float4*>(&Bs[kk][tx * TN]);
            *reinterpret_cast<float4*>(&b[4]) =
                *reinterpret_cast<const float4*>(&Bs[kk][tx * TN + 4]);
#pragma unroll
            for (int i = 0; i < TM; i++)
#pragma unroll
                for (int j = 0; j < TN; j++)
                    acc[i][j] = fmaf(a[i], b[j], acc[i][j]);
        }
        __syncthreads();
    }

    // Effective bias: b_eff[0] = 2*bias[0], else bias[i]. Broadcast loads (L1/L2 hit).
    float be[8];
#pragma unroll
    for (int i = 0; i < 8; i++) be[i] = bias[i];
    be[0] += be[0];

    // Fused segmented EXCLUSIVE cumsum over the thread's 8 rows (one block),
    // plus bias add. Row (blockRow + ty*8 + i) has block-position p == i.
    float run[TN];
#pragma unroll
    for (int j = 0; j < TN; j++) run[j] = 0.f;

#pragma unroll
    for (int i = 0; i < TM; i++) {
        int row = blockRow + ty * TM + i;
        float* op = &out[row * T + blockCol + tx * TN];
        float4 o0, o1;
        o0.x = run[0] + be[i]; o0.y = run[1] + be[i];
        o0.z = run[2] + be[i]; o0.w = run[3] + be[i];
        o1.x = run[4] + be[i]; o1.y = run[5] + be[i];
        o1.z = run[6] + be[i]; o1.w = run[7] + be[i];
        *reinterpret_cast<float4*>(op)     = o0;
        *reinterpret_cast<float4*>(op + 4) = o1;
#pragma unroll
        for (int j = 0; j < TN; j++) run[j] += acc[i][j];
    }
}

extern "C" void kernel_launch(void* const* d_in, const int* in_sizes, int n_in,
                              void* d_out, int out_size)
{
    const float* A    = (const float*)d_in[0];   // seq_vector [N,S,E] = [M,K]
    const float* W    = (const float*)d_in[1];   // [T, K]
    const float* bias = (const float*)d_in[2];   // [8]
    float* out = (float*)d_out;                  // [M, T]

    const int K = 256;
    const int T = 256;
    const int M = in_sizes[0] / K;               // 65536

    dim3 grid(T / BN, M / BM);                   // (2, 512)
    block_conv_sgemm_kernel<<<grid, THREADS>>>(A, W, bias, out, M, K, T);
}

// round 3
// speedup vs baseline: 2.2090x; 2.2090x over previous
#include <cuda_runtime.h>
#include <cuda_bf16.h>
#include <cuda_pipeline.h>
#include <cstdint>

// ============================================================================
// BlockConvolutionLean via mma.sync (legacy HMMA path — tcgen05 is not
// available under the harness's compute_103 virtual arch).
//   out = segmented-exclusive-cumsum_8( A @ W^T ) + b_eff, b_eff[0]=2*bias[0]
//   A [65536,256] f32, W [256,256] f32 row-major ([t,k]), out [65536,256] f32.
// Split-bf16: A=Ahi+Alo, W=Whi+Wlo;  C = Ahi*Whi + Alo*Whi + Ahi*Wlo.
// A split is fused into the GEMM tile fill; W pre-split once (tiny).
// ============================================================================

#define MROWS 65536
#define KD 256
#define ND 256
#define BM 128
#define BN 128
#define BKF 64              // fp32 K per chunk
#define NCH (KD / BKF)      // 4
#define THREADS 256

// W split scratch (allocation-free rule: __device__ globals)
__device__ __nv_bfloat16 g_Whi[ND * KD];
__device__ __nv_bfloat16 g_Wlo[ND * KD];

// Per-stage smem layout (bytes): Ahi | Alo | Whi | Wlo, 16KB each
#define OFF_AHI 0
#define OFF_ALO 16384
#define OFF_WHI 32768
#define OFF_WLO 49152
#define STAGE   65536
#define SMEM_TOTAL (2 * STAGE)   // 128 KB dynamic

// ---------------------------------------------------------------------------
__device__ __forceinline__ uint32_t smem_u32(const void* p) {
    uint32_t a;
    asm("{ .reg .u64 t; cvta.to.shared.u64 t, %1; cvt.u32.u64 %0, t; }"
        : "=r"(a) : "l"(p));
    return a;
}
__device__ __forceinline__ void ldsm_x4(uint32_t* r, uint32_t addr) {
    asm volatile("ldmatrix.sync.aligned.m8n8.x4.shared.b16 {%0,%1,%2,%3}, [%4];"
                 : "=r"(r[0]), "=r"(r[1]), "=r"(r[2]), "=r"(r[3]) : "r"(addr));
}
__device__ __forceinline__ void ldsm_x2(uint32_t* r, uint32_t addr) {
    asm volatile("ldmatrix.sync.aligned.m8n8.x2.shared.b16 {%0,%1}, [%2];"
                 : "=r"(r[0]), "=r"(r[1]) : "r"(addr));
}
__device__ __forceinline__ void mma_bf16(float* c, const uint32_t* a, const uint32_t* b) {
    asm volatile("mma.sync.aligned.m16n8k16.row.col.f32.bf16.bf16.f32 "
                 "{%0,%1,%2,%3}, {%4,%5,%6,%7}, {%8,%9}, {%0,%1,%2,%3};"
                 : "+f"(c[0]), "+f"(c[1]), "+f"(c[2]), "+f"(c[3])
                 : "r"(a[0]), "r"(a[1]), "r"(a[2]), "r"(a[3]), "r"(b[0]), "r"(b[1]));
}
__device__ __forceinline__ unsigned pck(__nv_bfloat16 a, __nv_bfloat16 b) {
    __nv_bfloat162 t(a, b);
    return *reinterpret_cast<unsigned*>(&t);
}

// ---------------------------------------------------------------------------
// W pre-split: fp32 -> (bf16 hi, bf16 lo)
// ---------------------------------------------------------------------------
__global__ __launch_bounds__(256) void split_convert_W(const float* __restrict__ W) {
    size_t i = ((size_t)blockIdx.x * 256 + threadIdx.x) * 8;
    float4 v0 = *reinterpret_cast<const float4*>(W + i);
    float4 v1 = *reinterpret_cast<const float4*>(W + i + 4);
    float f[8] = {v0.x, v0.y, v0.z, v0.w, v1.x, v1.y, v1.z, v1.w};
    __nv_bfloat16 hi[8], lo[8];
#pragma unroll
    for (int j = 0; j < 8; j++) {
        hi[j] = __float2bfloat16(f[j]);
        lo[j] = __float2bfloat16(f[j] - __bfloat162float(hi[j]));
    }
    uint4 uh, ul;
    uh.x = pck(hi[0], hi[1]); uh.y = pck(hi[2], hi[3]);
    uh.z = pck(hi[4], hi[5]); uh.w = pck(hi[6], hi[7]);
    ul.x = pck(lo[0], lo[1]); ul.y = pck(lo[2], lo[3]);
    ul.z = pck(lo[4], lo[5]); ul.w = pck(lo[6], lo[7]);
    *reinterpret_cast<uint4*>(g_Whi + i) = uh;
    *reinterpret_cast<uint4*>(g_Wlo + i) = ul;
}

// ---------------------------------------------------------------------------
// Fused GEMM + blockwise exclusive scan
// ---------------------------------------------------------------------------
__device__ __forceinline__ void w_fill(char* smem, int s, int c, int n0, int tid) {
    char* base = smem + (size_t)s * STAGE;
    const int k0 = c * BKF;
#pragma unroll
    for (int i = 0; i < 4; i++) {
        int v = tid + i * THREADS;        // 0..1023
        int row = v >> 3, kc = v & 7;
        uint32_t sw = (uint32_t)row * 128 + ((kc * 16) ^ ((row & 7) << 4));
        __pipeline_memcpy_async(base + OFF_WHI + sw,
                                g_Whi + (size_t)(n0 + row) * KD + k0 + kc * 8, 16);
        __pipeline_memcpy_async(base + OFF_WLO + sw,
                                g_Wlo + (size_t)(n0 + row) * KD + k0 + kc * 8, 16);
    }
}

__device__ __forceinline__ void a_sts(char* smem, int s, const float4* pf, int tid) {
    char* base = smem + (size_t)s * STAGE;
    const int row = tid >> 1, half = tid & 1;
#pragma unroll
    for (int j = 0; j < 4; j++) {
        const float f[8] = {pf[2*j].x, pf[2*j].y, pf[2*j].z, pf[2*j].w,
                            pf[2*j+1].x, pf[2*j+1].y, pf[2*j+1].z, pf[2*j+1].w};
        __nv_bfloat16 hi[8], lo[8];
#pragma unroll
        for (int e = 0; e < 8; e++) {
            hi[e] = __float2bfloat16(f[e]);
            lo[e] = __float2bfloat16(f[e] - __bfloat162float(hi[e]));
        }
        uint4 uh, ul;
        uh.x = pck(hi[0], hi[1]); uh.y = pck(hi[2], hi[3]);
        uh.z = pck(hi[4], hi[5]); uh.w = pck(hi[6], hi[7]);
        ul.x = pck(lo[0], lo[1]); ul.y = pck(lo[2], lo[3]);
        ul.z = pck(lo[4], lo[5]); ul.w = pck(lo[6], lo[7]);
        int kc = half * 4 + j;
        uint32_t sw = (uint32_t)row * 128 + ((kc * 16) ^ ((row & 7) << 4));
        *reinterpret_cast<uint4*>(base + OFF_AHI + sw) = uh;
        *reinterpret_cast<uint4*>(base + OFF_ALO + sw) = ul;
    }
}

__global__ __launch_bounds__(THREADS, 1)
void bc_mma(const float* __restrict__ A, const float* __restrict__ bias,
            float* __restrict__ out)
{
    extern __shared__ __align__(1024) char smem[];
    const int tid = threadIdx.x;
    const int lane = tid & 31, w = tid >> 5;
    const int wm = w >> 1, wn = w & 1;           // 4 x 2 warp grid
    const int m0 = blockIdx.x * BM;
    const int n0 = blockIdx.y * BN;

    float acc[2][8][4];
#pragma unroll
    for (int mf = 0; mf < 2; mf++)
#pragma unroll
        for (int nf = 0; nf < 8; nf++)
#pragma unroll
            for (int e = 0; e < 4; e++) acc[mf][nf][e] = 0.f;

    // Per-lane smem address components (swizzle xor constant = (lane&7)<<4)
    const uint32_t sb0 = smem_u32(smem);
    const uint32_t xorv = (uint32_t)(lane & 7) << 4;
    // A ldmatrix: row = wm*32 + mf*16 + (lane&15), col-sel = (lane>>4)<<4
    const uint32_t a_row = (uint32_t)(wm * 32 + (lane & 15));
    const uint32_t a_csel = ((uint32_t)(lane >> 4)) << 4;
    // B ldmatrix: row = wn*64 + nf*8 + (lane&7), col-sel = ((lane>>3)&1)<<4
    const uint32_t b_row = (uint32_t)(wn * 64 + (lane & 7));
    const uint32_t b_csel = ((uint32_t)((lane >> 3) & 1)) << 4;

    // A global pointer for this thread (row tid>>1, k-half tid&1)
    const float* ap = A + (size_t)(m0 + (tid >> 1)) * KD + (tid & 1) * 32;

    // ---- prologue: chunk 0 into stage 0 ----
    w_fill(smem, 0, 0, n0, tid);
    __pipeline_commit();
    float4 pf[8];
#pragma unroll
    for (int j = 0; j < 8; j++)
        pf[j] = *reinterpret_cast<const float4*>(ap + j * 4);
    a_sts(smem, 0, pf, tid);
    __pipeline_wait_prior(0);
    __syncthreads();

#pragma unroll
    for (int c = 0; c < NCH; c++) {
        const int s = c & 1;
        if (c < NCH - 1) {
            w_fill(smem, 1 - s, c + 1, n0, tid);
            __pipeline_commit();
#pragma unroll
            for (int j = 0; j < 8; j++)
                pf[j] = *reinterpret_cast<const float4*>(ap + (c + 1) * BKF + j * 4);
        }

        // ---- compute chunk c from stage s ----
        const uint32_t sb = sb0 + (uint32_t)s * STAGE;
#pragma unroll
        for (int step = 0; step < 4; step++) {
            const uint32_t qa = (uint32_t)step * 32 + a_csel;
            const uint32_t qb = (uint32_t)step * 32 + b_csel;
            uint32_t ah[2][4], al[2][4];
#pragma unroll
            for (int mf = 0; mf < 2; mf++) {
                uint32_t rbyte = (a_row + mf * 16) * 128 + (qa ^ xorv);
                ldsm_x4(ah[mf], sb + OFF_AHI + rbyte);
                ldsm_x4(al[mf], sb + OFF_ALO + rbyte);
            }
#pragma unroll
            for (int nf = 0; nf < 8; nf++) {
                uint32_t rbyte = (b_row + nf * 8) * 128 + (qb ^ xorv);
                uint32_t bh[2], bl[2];
                ldsm_x2(bh, sb + OFF_WHI + rbyte);
                ldsm_x2(bl, sb + OFF_WLO + rbyte);
#pragma unroll
                for (int mf = 0; mf < 2; mf++) {
                    mma_bf16(acc[mf][nf], ah[mf], bh);
                    mma_bf16(acc[mf][nf], al[mf], bh);
                    mma_bf16(acc[mf][nf], ah[mf], bl);
                }
            }
        }

        if (c < NCH - 1) {
            a_sts(smem, 1 - s, pf, tid);
            __pipeline_wait_prior(0);
            __syncthreads();
        }
    }

    // ---- epilogue: segmented exclusive scan over 8-row blocks + bias ----
    const int p = lane >> 2;                 // block position 0..7
    float be = bias[p];
    if (p == 0) be += be;                    // b_eff[0] = 2*bias[0]

#pragma unroll
    for (int mf = 0; mf < 2; mf++) {
#pragma unroll
        for (int nf = 0; nf < 8; nf++) {
            float e[4];
#pragma unroll
            for (int q = 0; q < 4; q++) {
                float v = acc[mf][nf][q];
                float sgm = v, t;
                t = __shfl_up_sync(0xffffffffu, sgm, 4);  if (p >= 1) sgm += t;
                t = __shfl_up_sync(0xffffffffu, sgm, 8);  if (p >= 2) sgm += t;
                t = __shfl_up_sync(0xffffffffu, sgm, 16); if (p >= 4) sgm += t;
                e[q] = sgm - v + be;
            }
            const int row0 = m0 + wm * 32 + mf * 16 + p;
            const int col  = n0 + wn * 64 + nf * 8 + (lane & 3) * 2;
            *reinterpret_cast<float2*>(out + (size_t)row0 * ND + col) =
                make_float2(e[0], e[1]);
            *reinterpret_cast<float2*>(out + (size_t)(row0 + 8) * ND + col) =
                make_float2(e[2], e[3]);
        }
    }
}

// ---------------------------------------------------------------------------
extern "C" void kernel_launch(void* const* d_in, const int* in_sizes, int n_in,
                              void* d_out, int out_size)
{
    const float* A    = (const float*)d_in[0];   // [65536, 256]
    const float* W    = (const float*)d_in[1];   // [256, 256]
    const float* bias = (const float*)d_in[2];   // [8]
    float* out = (float*)d_out;

    split_convert_W<<<(ND * KD) / (8 * 256), 256>>>(W);

    cudaFuncSetAttribute(bc_mma, cudaFuncAttributeMaxDynamicSharedMemorySize,
                         SMEM_TOTAL);
    dim3 grid(MROWS / BM, ND / BN);              // (512, 2)
    bc_mma<<<grid, THREADS, SMEM_TOTAL>>>(A, bias, out);
    (void)in_sizes; (void)n_in; (void)out_size;
}

// round 4
// speedup vs baseline: 2.3775x; 1.0763x over previous
#include <cuda_runtime.h>
#include <cuda_fp16.h>
#include <cstdint>

// ============================================================================
// BlockConvolutionLean, single-term fp16 mma.sync:
//   out = segmented-exclusive-cumsum_8( A @ W^T ) + b_eff, b_eff[0]=2*bias[0]
//   A [65536,256] f32, W [256,256] f32 ([t,k]), out [65536,256] f32.
// C = fp16(A) @ fp16(W)^T with fp32 accumulate. RMS rel err ~4e-4 (<1e-3).
// W tile converted per-CTA in prologue; A conversion fused into chunk fill.
// ============================================================================

#define MROWS 65536
#define KD 256
#define ND 256
#define BM 128
#define BN 128
#define BKF 64              // fp32 K per chunk
#define NCH (KD / BKF)      // 4
#define THREADS 256

// smem: W regions (4 chunks x 16KB, resident all kernel) + A double buffer
#define OFF_W 0
#define W_REGION 16384
#define OFF_A 65536
#define A_STAGE 16384
#define SMEM_TOTAL (OFF_A + 2 * A_STAGE)   // 96 KB

// ---------------------------------------------------------------------------
__device__ __forceinline__ uint32_t smem_u32(const void* p) {
    uint32_t a;
    asm("{ .reg .u64 t; cvta.to.shared.u64 t, %1; cvt.u32.u64 %0, t; }"
        : "=r"(a) : "l"(p));
    return a;
}
__device__ __forceinline__ void ldsm_x4(uint32_t* r, uint32_t addr) {
    asm volatile("ldmatrix.sync.aligned.m8n8.x4.shared.b16 {%0,%1,%2,%3}, [%4];"
                 : "=r"(r[0]), "=r"(r[1]), "=r"(r[2]), "=r"(r[3]) : "r"(addr));
}
__device__ __forceinline__ void mma_f16(float* c, const uint32_t* a, const uint32_t* b) {
    asm volatile("mma.sync.aligned.m16n8k16.row.col.f32.f16.f16.f32 "
                 "{%0,%1,%2,%3}, {%4,%5,%6,%7}, {%8,%9}, {%0,%1,%2,%3};"
                 : "+f"(c[0]), "+f"(c[1]), "+f"(c[2]), "+f"(c[3])
                 : "r"(a[0]), "r"(a[1]), "r"(a[2]), "r"(a[3]), "r"(b[0]), "r"(b[1]));
}

// Convert 32 fp32 -> 32 fp16 and store into a [128 x 128B] swizzled tile.
// Thread covers row (tid>>1), k-half (tid&1)*32.
__device__ __forceinline__ void tile_sts_f16(char* dst_base, const float4* pf, int tid) {
    const int row = tid >> 1, half = tid & 1;
    const uint32_t rowxor = (uint32_t)(row & 7) << 4;
#pragma unroll
    for (int j = 0; j < 4; j++) {
        __half2 h0 = __floats2half2_rn(pf[2*j].x,   pf[2*j].y);
        __half2 h1 = __floats2half2_rn(pf[2*j].z,   pf[2*j].w);
        __half2 h2 = __floats2half2_rn(pf[2*j+1].x, pf[2*j+1].y);
        __half2 h3 = __floats2half2_rn(pf[2*j+1].z, pf[2*j+1].w);
        uint4 u;
        u.x = *reinterpret_cast<uint32_t*>(&h0);
        u.y = *reinterpret_cast<uint32_t*>(&h1);
        u.z = *reinterpret_cast<uint32_t*>(&h2);
        u.w = *reinterpret_cast<uint32_t*>(&h3);
        uint32_t off = (uint32_t)row * 128 + (uint32_t)((half * 64 + j * 16) ^ rowxor);
        *reinterpret_cast<uint4*>(dst_base + off) = u;
    }
}

// ---------------------------------------------------------------------------
__global__ __launch_bounds__(THREADS, 1)
void bc_mma(const float* __restrict__ A, const float* __restrict__ W,
            const float* __restrict__ bias, float* __restrict__ out)
{
    extern __shared__ __align__(1024) char smem[];
    const int tid = threadIdx.x;
    const int lane = tid & 31, w = tid >> 5;
    const int wm = w >> 1, wn = w & 1;            // 4 x 2 warp grid
    const int n0 = blockIdx.x * BN;               // gridDim.x = 2 (fast dim)
    const int m0 = blockIdx.y * BM;

    const int p = lane >> 2;                      // block position 0..7
    float be = __ldg(bias + p);
    if (p == 0) be += be;                         // b_eff[0] = 2*bias[0]

    float acc[2][8][4] = {};

    // ---- prologue: A chunk0 prefetch + full W tile (4 chunks) conversion ----
    const int row = tid >> 1, half = tid & 1;
    const float* ap = A + (size_t)(m0 + row) * KD + half * 32;
    const float* wp = W + (size_t)(n0 + row) * KD + half * 32;

    float4 pf[8];
#pragma unroll
    for (int j = 0; j < 8; j++) pf[j] = *reinterpret_cast<const float4*>(ap + j * 4);

#pragma unroll
    for (int c = 0; c < NCH; c++) {
        float4 wf[8];
#pragma unroll
        for (int j = 0; j < 8; j++)
            wf[j] = *reinterpret_cast<const float4*>(wp + c * BKF + j * 4);
        tile_sts_f16(smem + OFF_W + c * W_REGION, wf, tid);
    }
    tile_sts_f16(smem + OFF_A, pf, tid);
    __syncthreads();

    // ---- per-lane ldmatrix address components ----
    const uint32_t sb = smem_u32(smem);
    const uint32_t xorv = (uint32_t)(lane & 7) << 4;
    const uint32_t a_row  = (uint32_t)(wm * 32 + (lane & 15));
    const uint32_t a_csel = ((uint32_t)(lane >> 4)) << 4;
    const uint32_t b_row  = (uint32_t)(wn * 64 + ((lane >> 4) << 3) + (lane & 7));
    const uint32_t b_csel = ((uint32_t)((lane >> 3) & 1)) << 4;

#pragma unroll
    for (int c = 0; c < NCH; c++) {
        const int s = c & 1;
        if (c < NCH - 1) {
#pragma unroll
            for (int j = 0; j < 8; j++)
                pf[j] = *reinterpret_cast<const float4*>(ap + (c + 1) * BKF + j * 4);
        }
        const uint32_t abase = sb + OFF_A + (uint32_t)s * A_STAGE;
        const uint32_t wbase = sb + OFF_W + (uint32_t)c * W_REGION;

#pragma unroll
        for (int step = 0; step < 4; step++) {
            uint32_t a[2][4];
#pragma unroll
            for (int mf = 0; mf < 2; mf++)
                ldsm_x4(a[mf], abase + (a_row + mf * 16) * 128 +
                               (((uint32_t)step * 32 + a_csel) ^ xorv));
#pragma unroll
            for (int nfp = 0; nfp < 4; nfp++) {
                uint32_t b[4];
                ldsm_x4(b, wbase + (b_row + nfp * 16) * 128 +
                           (((uint32_t)step * 32 + b_csel) ^ xorv));
                mma_f16(acc[0][2*nfp],     a[0], b);
                mma_f16(acc[0][2*nfp + 1], a[0], b + 2);
                mma_f16(acc[1][2*nfp],     a[1], b);
                mma_f16(acc[1][2*nfp + 1], a[1], b + 2);
            }
        }

        if (c < NCH - 1) {
            tile_sts_f16(smem + OFF_A + (1 - s) * A_STAGE, pf, tid);
            __syncthreads();
        }
    }

    // ---- epilogue: segmented exclusive scan over 8-row blocks + bias ----
#pragma unroll
    for (int mf = 0; mf < 2; mf++) {
#pragma unroll
        for (int nf = 0; nf < 8; nf++) {
            float e[4];
#pragma unroll
            for (int q = 0; q < 4; q++) {
                float v = acc[mf][nf][q];
                float sgm = v, t;
                t = __shfl_up_sync(0xffffffffu, sgm, 4);  if (p >= 1) sgm += t;
                t = __shfl_up_sync(0xffffffffu, sgm, 8);  if (p >= 2) sgm += t;
                t = __shfl_up_sync(0xffffffffu, sgm, 16); if (p >= 4) sgm += t;
                e[q] = sgm - v + be;
            }
            const int row0 = m0 + wm * 32 + mf * 16 + p;
            const int col  = n0 + wn * 64 + nf * 8 + (lane & 3) * 2;
            *reinterpret_cast<float2*>(out + (size_t)row0 * ND + col) =
                make_float2(e[0], e[1]);
            *reinterpret_cast<float2*>(out + (size_t)(row0 + 8) * ND + col) =
                make_float2(e[2], e[3]);
        }
    }
}

// ---------------------------------------------------------------------------
extern "C" void kernel_launch(void* const* d_in, const int* in_sizes, int n_in,
                              void* d_out, int out_size)
{
    const float* A    = (const float*)d_in[0];   // [65536, 256]
    const float* W    = (const float*)d_in[1];   // [256, 256]
    const float* bias = (const float*)d_in[2];   // [8]
    float* out = (float*)d_out;

    cudaFuncSetAttribute(bc_mma, cudaFuncAttributeMaxDynamicSharedMemorySize,
                         SMEM_TOTAL);
    dim3 grid(ND / BN, MROWS / BM);              // (2, 512): N fastest -> A-tile reuse in L2
    bc_mma<<<grid, THREADS, SMEM_TOTAL>>>(A, W, bias, out);
    (void)in_sizes; (void)n_in; (void)out_size;
}

// round 5
// speedup vs baseline: 3.9128x; 1.6457x over previous
#include <cuda_runtime.h>
#include <cuda_fp16.h>
#include <cuda_pipeline.h>
#include <cstdint>

// ============================================================================
// BlockConvolutionLean, fp16 mma.sync, A streamed directly from global:
//   out = segmented-exclusive-cumsum_8( A @ W^T ) + b_eff, b_eff[0]=2*bias[0]
//   A [65536,256] f32, W [256,256] f32 ([t,k]), out [65536,256] f32.
// C = fp16(A) @ fp16(W)^T, fp32 accumulate (measured rel_err ~2.8e-4).
// - W converted fp32->fp16 once (micro-kernel), resident in smem per CTA.
// - A fragments fed by coalesced LDG.64 + in-register cvt: no STS/LDS for A,
//   no mainloop __syncthreads at all.
// - BN = 256 (full N): A read from DRAM exactly once.
// ============================================================================

#define MROWS 65536
#define KD 256
#define ND 256
#define BM 128
#define THREADS 256

#define W_REGION 32768               // one K=64 chunk: 256 rows x 128B
#define SMEM_TOTAL (4 * W_REGION)    // 128 KB (full W fp16, swizzled)

__device__ __half g_Whf[ND * KD];    // pre-converted W (fp16)

// ---------------------------------------------------------------------------
__device__ __forceinline__ uint32_t smem_u32(const void* p) {
    uint32_t a;
    asm("{ .reg .u64 t; cvta.to.shared.u64 t, %1; cvt.u32.u64 %0, t; }"
        : "=r"(a) : "l"(p));
    return a;
}
__device__ __forceinline__ void ldsm_x4(uint32_t* r, uint32_t addr) {
    asm volatile("ldmatrix.sync.aligned.m8n8.x4.shared.b16 {%0,%1,%2,%3}, [%4];"
                 : "=r"(r[0]), "=r"(r[1]), "=r"(r[2]), "=r"(r[3]) : "r"(addr));
}
__device__ __forceinline__ void mma_f16(float* c, const uint32_t* a, const uint32_t* b) {
    asm volatile("mma.sync.aligned.m16n8k16.row.col.f32.f16.f16.f32 "
                 "{%0,%1,%2,%3}, {%4,%5,%6,%7}, {%8,%9}, {%0,%1,%2,%3};"
                 : "+f"(c[0]), "+f"(c[1]), "+f"(c[2]), "+f"(c[3])
                 : "r"(a[0]), "r"(a[1]), "r"(a[2]), "r"(a[3]), "r"(b[0]), "r"(b[1]));
}
__device__ __forceinline__ uint32_t h2u(__half2 h) {
    return *reinterpret_cast<uint32_t*>(&h);
}

// ---------------------------------------------------------------------------
__global__ __launch_bounds__(256) void convert_W(const float* __restrict__ W) {
    int i = (blockIdx.x * 256 + threadIdx.x) * 4;
    float4 v = *reinterpret_cast<const float4*>(W + i);
    __half2 h0 = __floats2half2_rn(v.x, v.y);
    __half2 h1 = __floats2half2_rn(v.z, v.w);
    uint2 u;
    u.x = *reinterpret_cast<uint32_t*>(&h0);
    u.y = *reinterpret_cast<uint32_t*>(&h1);
    *reinterpret_cast<uint2*>(g_Whf + i) = u;
}

// ---------------------------------------------------------------------------
__global__ __launch_bounds__(THREADS, 1)
void bc_mma(const float* __restrict__ A, const float* __restrict__ bias,
            float* __restrict__ out)
{
    extern __shared__ __align__(1024) char smem[];
    const int tid = threadIdx.x;
    const int lane = tid & 31, w = tid >> 5;
    const int wm = w >> 1, wn = w & 1;        // 4(m) x 2(n); warp tile 32 x 128
    const int m0 = blockIdx.x * BM;

    // A fragment base: row = m0 + wm*32 + (lane>>2), col = (lane&3)*2
    const float* a0 = A + (size_t)(m0 + wm * 32 + (lane >> 2)) * KD + (lane & 3) * 2;

    // ---- prefetch A step 0 (overlaps W cp.async) ----
    float2 afn[8];
#pragma unroll
    for (int mf = 0; mf < 2; mf++) {
        const float* p = a0 + mf * 16 * KD;
        afn[mf * 4 + 0] = *reinterpret_cast<const float2*>(p);
        afn[mf * 4 + 1] = *reinterpret_cast<const float2*>(p + 8 * KD);
        afn[mf * 4 + 2] = *reinterpret_cast<const float2*>(p + 8);
        afn[mf * 4 + 3] = *reinterpret_cast<const float2*>(p + 8 * KD + 8);
    }

    // ---- fill W smem (full 256x256 fp16, 4 K-regions, SW swizzled) ----
#pragma unroll
    for (int i = 0; i < 32; i++) {
        int v = tid + i * THREADS;            // 0..8191
        int c = v >> 11;                      // region 0..3
        int r = (v >> 3) & 255;               // row 0..255
        int seg = v & 7;                      // 16B segment
        uint32_t off = (uint32_t)c * W_REGION + (uint32_t)r * 128 +
                       (uint32_t)((seg * 16) ^ ((r & 7) << 4));
        __pipeline_memcpy_async(smem + off,
                                g_Whf + (size_t)r * KD + c * 64 + seg * 8, 16);
    }
    __pipeline_commit();

    float acc[2][16][4] = {};

    const uint32_t sb = smem_u32(smem);
    const uint32_t xorv  = (uint32_t)(lane & 7) << 4;
    const uint32_t b_row = (uint32_t)(wn * 128 + ((lane >> 4) << 3) + (lane & 7));
    const uint32_t b_csel = ((uint32_t)((lane >> 3) & 1)) << 4;

    __pipeline_wait_prior(0);
    __syncthreads();                          // only barrier in the kernel

    // ---- mainloop: 16 k-steps of 16, barrier-free ----
#pragma unroll
    for (int t = 0; t < 16; t++) {
        float2 af[8];
#pragma unroll
        for (int j = 0; j < 8; j++) af[j] = afn[j];
        if (t < 15) {
#pragma unroll
            for (int mf = 0; mf < 2; mf++) {
                const float* p = a0 + mf * 16 * KD + (t + 1) * 16;
                afn[mf * 4 + 0] = *reinterpret_cast<const float2*>(p);
                afn[mf * 4 + 1] = *reinterpret_cast<const float2*>(p + 8 * KD);
                afn[mf * 4 + 2] = *reinterpret_cast<const float2*>(p + 8);
                afn[mf * 4 + 3] = *reinterpret_cast<const float2*>(p + 8 * KD + 8);
            }
        }
        uint32_t ah[2][4];
#pragma unroll
        for (int j = 0; j < 8; j++)
            ah[j >> 2][j & 3] = h2u(__floats2half2_rn(af[j].x, af[j].y));

        const uint32_t wbase = sb + (uint32_t)(t >> 2) * W_REGION;
        const uint32_t ksel  = (((uint32_t)(t & 3) * 32) + b_csel) ^ xorv;

        uint32_t b[8][4];
#pragma unroll
        for (int nfp = 0; nfp < 8; nfp++)
            ldsm_x4(b[nfp], wbase + (b_row + nfp * 16) * 128 + ksel);

#pragma unroll
        for (int nfp = 0; nfp < 8; nfp++) {
            mma_f16(acc[0][2 * nfp],     ah[0], b[nfp]);
            mma_f16(acc[0][2 * nfp + 1], ah[0], b[nfp] + 2);
            mma_f16(acc[1][2 * nfp],     ah[1], b[nfp]);
            mma_f16(acc[1][2 * nfp + 1], ah[1], b[nfp] + 2);
        }
    }

    // ---- epilogue: segmented exclusive scan over 8-row blocks + bias ----
    const int p = lane >> 2;                  // block position 0..7
    float be = __ldg(bias + p);
    if (p == 0) be += be;                     // b_eff[0] = 2*bias[0]

#pragma unroll
    for (int mf = 0; mf < 2; mf++) {
#pragma unroll
        for (int nf = 0; nf < 16; nf++) {
            float e[4];
#pragma unroll
            for (int q = 0; q < 4; q++) {
                float v = acc[mf][nf][q];
                float sgm = v, t;
                t = __shfl_up_sync(0xffffffffu, sgm, 4);  if (p >= 1) sgm += t;
                t = __shfl_up_sync(0xffffffffu, sgm, 8);  if (p >= 2) sgm += t;
                t = __shfl_up_sync(0xffffffffu, sgm, 16); if (p >= 4) sgm += t;
                e[q] = sgm - v + be;
            }
            const int row0 = m0 + wm * 32 + mf * 16 + p;
            const int col  = wn * 128 + nf * 8 + (lane & 3) * 2;
            *reinterpret_cast<float2*>(out + (size_t)row0 * ND + col) =
                make_float2(e[0], e[1]);
            *reinterpret_cast<float2*>(out + (size_t)(row0 + 8) * ND + col) =
                make_float2(e[2], e[3]);
        }
    }
}

// ---------------------------------------------------------------------------
extern "C" void kernel_launch(void* const* d_in, const int* in_sizes, int n_in,
                              void* d_out, int out_size)
{
    const float* A    = (const float*)d_in[0];   // [65536, 256]
    const float* W    = (const float*)d_in[1];   // [256, 256]
    const float* bias = (const float*)d_in[2];   // [8]
    float* out = (float*)d_out;

    convert_W<<<(ND * KD) / (4 * 256), 256>>>(W);

    cudaFuncSetAttribute(bc_mma, cudaFuncAttributeMaxDynamicSharedMemorySize,
                         SMEM_TOTAL);
    bc_mma<<<MROWS / BM, THREADS, SMEM_TOTAL>>>(A, bias, out);
    (void)in_sizes; (void)n_in; (void)out_size;
}

// round 6
// speedup vs baseline: 4.2520x; 1.0867x over previous
#include <cuda_runtime.h>
#include <cuda_fp16.h>
#include <cuda_pipeline.h>
#include <cstdint>

// ============================================================================
// BlockConvolutionLean, fp16 mma.sync:
//   out = segmented-exclusive-cumsum_8( A @ W^T ) + b_eff, b_eff[0]=2*bias[0]
// - W fp16 pre-converted, fully smem-resident (128 KB, 4 K-regions).
// - A: coalesced LDG.128 (full-line) -> cvt fp16 -> swizzled STS -> ldmatrix,
//   3-stage chunk buffer, register prefetch 1 chunk ahead, 1 sync per chunk.
// - Warp tile 64x64 (2m x 4n warps) minimizes ldmatrix traffic.
// ============================================================================

#define MROWS 65536
#define KD 256
#define ND 256
#define BM 128
#define THREADS 256
#define NCH 4                         // K chunks of 64 fp32

#define W_REGION 32768                // 256 rows x 128B (one K=64 chunk)
#define OFF_A (4 * W_REGION)          // 131072
#define A_STAGE 16384                 // 128 rows x 128B
#define SMEM_TOTAL (OFF_A + 3 * A_STAGE)   // 180224 B

__device__ __half g_Whf[ND * KD];     // pre-converted W (fp16)

// ---------------------------------------------------------------------------
__device__ __forceinline__ uint32_t smem_u32(const void* p) {
    uint32_t a;
    asm("{ .reg .u64 t; cvta.to.shared.u64 t, %1; cvt.u32.u64 %0, t; }"
        : "=r"(a) : "l"(p));
    return a;
}
__device__ __forceinline__ void ldsm_x4(uint32_t* r, uint32_t addr) {
    asm volatile("ldmatrix.sync.aligned.m8n8.x4.shared.b16 {%0,%1,%2,%3}, [%4];"
                 : "=r"(r[0]), "=r"(r[1]), "=r"(r[2]), "=r"(r[3]) : "r"(addr));
}
__device__ __forceinline__ void mma_f16(float* c, const uint32_t* a, const uint32_t* b) {
    asm volatile("mma.sync.aligned.m16n8k16.row.col.f32.f16.f16.f32 "
                 "{%0,%1,%2,%3}, {%4,%5,%6,%7}, {%8,%9}, {%0,%1,%2,%3};"
                 : "+f"(c[0]), "+f"(c[1]), "+f"(c[2]), "+f"(c[3])
                 : "r"(a[0]), "r"(a[1]), "r"(a[2]), "r"(a[3]), "r"(b[0]), "r"(b[1]));
}
__device__ __forceinline__ uint32_t h2u(__half2 h) {
    return *reinterpret_cast<uint32_t*>(&h);
}

// ---------------------------------------------------------------------------
__global__ __launch_bounds__(256) void convert_W(const float* __restrict__ W) {
    int i = (blockIdx.x * 256 + threadIdx.x) * 4;
    float4 v = *reinterpret_cast<const float4*>(W + i);
    __half2 h0 = __floats2half2_rn(v.x, v.y);
    __half2 h1 = __floats2half2_rn(v.z, v.w);
    uint2 u;
    u.x = *reinterpret_cast<uint32_t*>(&h0);
    u.y = *reinterpret_cast<uint32_t*>(&h1);
    *reinterpret_cast<uint2*>(g_Whf + i) = u;
}

// ---------------------------------------------------------------------------
// A chunk: convert prefetched fp32 regs -> fp16, store swizzled.
// Warp w owns rows w*16..w*16+15; per j: rows w*16+2j+(lane>>4), lane&15 = float4 idx.
__device__ __forceinline__ void sts_a(char* stage, const float4* pf, int w, int lane) {
    const int rbase = w * 16 + (lane >> 4);
    const uint32_t colb = (uint32_t)(lane & 15) * 8;
#pragma unroll
    for (int j = 0; j < 8; j++) {
        const int row = rbase + 2 * j;
        __half2 h0 = __floats2half2_rn(pf[j].x, pf[j].y);
        __half2 h1 = __floats2half2_rn(pf[j].z, pf[j].w);
        uint2 u;
        u.x = h2u(h0); u.y = h2u(h1);
        uint32_t off = (uint32_t)row * 128 + (colb ^ (uint32_t)((row & 7) << 4));
        *reinterpret_cast<uint2*>(stage + off) = u;
    }
}

// ---------------------------------------------------------------------------
__global__ __launch_bounds__(THREADS, 1)
void bc_mma(const float* __restrict__ A, const float* __restrict__ bias,
            float* __restrict__ out)
{
    extern __shared__ __align__(1024) char smem[];
    const int tid = threadIdx.x;
    const int lane = tid & 31, w = tid >> 5;
    const int wm = w >> 2, wn = w & 3;        // 2(m) x 4(n); warp tile 64 x 64
    const int m0 = blockIdx.x * BM;

    // ---- W fill: full 256x256 fp16, 4 K-regions, swizzled, via cp.async ----
#pragma unroll
    for (int i = 0; i < 32; i++) {
        int v = tid + i * THREADS;            // 0..8191
        int c = v >> 11;                      // region 0..3
        int r = (v >> 3) & 255;               // row 0..255
        int seg = v & 7;                      // 16B segment
        uint32_t off = (uint32_t)c * W_REGION + (uint32_t)r * 128 +
                       (uint32_t)((seg * 16) ^ ((r & 7) << 4));
        __pipeline_memcpy_async(smem + off,
                                g_Whf + (size_t)r * KD + c * 64 + seg * 8, 16);
    }
    __pipeline_commit();

    // ---- A global base: warp covers rows w*16..+15, fully coalesced LDG.128 ----
    const float* ag = A + (size_t)(m0 + w * 16 + (lane >> 4)) * KD + (lane & 15) * 4;

    float4 pf[8];
#pragma unroll
    for (int j = 0; j < 8; j++)               // chunk 0
        pf[j] = *reinterpret_cast<const float4*>(ag + j * 2 * KD);
    sts_a(smem + OFF_A, pf, w, lane);
#pragma unroll
    for (int j = 0; j < 8; j++)               // chunk 1 prefetch
        pf[j] = *reinterpret_cast<const float4*>(ag + j * 2 * KD + 64);

    float acc[2][8][4] = {};   // [mf pair? no] -- see below: acc[4][8][4] needed
    // NOTE: using acc4 below
    (void)acc;

    float acc4[4][8][4] = {};

    const uint32_t sb = smem_u32(smem);
    const uint32_t xorv   = (uint32_t)(lane & 7) << 4;
    const uint32_t a_row  = (uint32_t)(wm * 64 + (lane & 15));
    const uint32_t a_csel = ((uint32_t)(lane >> 4)) << 4;
    const uint32_t b_row  = (uint32_t)(wn * 64 + ((lane >> 4) << 3) + (lane & 7));
    const uint32_t b_csel = ((uint32_t)((lane >> 3) & 1)) << 4;

    __pipeline_wait_prior(0);
    __syncthreads();

    // ---- mainloop: 4 chunks x 4 k-steps; 1 sync per chunk ----
#pragma unroll
    for (int c = 0; c < NCH; c++) {
        if (c < NCH - 1) {
            // stage (c+1)%3 was last used by chunk c-2; sync at end of chunk
            // c-1 guarantees all warps are past it.
            sts_a(smem + OFF_A + ((c + 1) % 3) * A_STAGE, pf, w, lane);
            if (c < NCH - 2) {
#pragma unroll
                for (int j = 0; j < 8; j++)
                    pf[j] = *reinterpret_cast<const float4*>(
                        ag + j * 2 * KD + (c + 2) * 64);
            }
        }

        const uint32_t abase = sb + OFF_A + (uint32_t)(c % 3) * A_STAGE;
        const uint32_t wbase = sb + (uint32_t)c * W_REGION;

#pragma unroll
        for (int s = 0; s < 4; s++) {
            const uint32_t ksa = (((uint32_t)s * 32) + a_csel) ^ xorv;
            const uint32_t ksb = (((uint32_t)s * 32) + b_csel) ^ xorv;
            uint32_t a[4][4], b[4][4];
#pragma unroll
            for (int mf = 0; mf < 4; mf++)
                ldsm_x4(a[mf], abase + (a_row + mf * 16) * 128 + ksa);
#pragma unroll
            for (int nfp = 0; nfp < 4; nfp++)
                ldsm_x4(b[nfp], wbase + (b_row + nfp * 16) * 128 + ksb);
#pragma unroll
            for (int mf = 0; mf < 4; mf++)
#pragma unroll
                for (int nfp = 0; nfp < 4; nfp++) {
                    mma_f16(acc4[mf][2 * nfp],     a[mf], b[nfp]);
                    mma_f16(acc4[mf][2 * nfp + 1], a[mf], b[nfp] + 2);
                }
        }
        __syncthreads();   // makes sts(c+1) visible; gates stage reuse
    }

    // ---- epilogue: segmented exclusive scan over 8-row blocks + bias ----
    const int p = lane >> 2;                  // block position 0..7
    float be = __ldg(bias + p);
    if (p == 0) be += be;                     // b_eff[0] = 2*bias[0]

#pragma unroll
    for (int mf = 0; mf < 4; mf++) {
#pragma unroll
        for (int nf = 0; nf < 8; nf++) {
            float e[4];
#pragma unroll
            for (int q = 0; q < 4; q++) {
                float v = acc4[mf][nf][q];
                float sgm = v, t;
                t = __shfl_up_sync(0xffffffffu, sgm, 4);  if (p >= 1) sgm += t;
                t = __shfl_up_sync(0xffffffffu, sgm, 8);  if (p >= 2) sgm += t;
                t = __shfl_up_sync(0xffffffffu, sgm, 16); if (p >= 4) sgm += t;
                e[q] = sgm - v + be;
            }
            const int row0 = m0 + wm * 64 + mf * 16 + p;
            const int col  = wn * 64 + nf * 8 + (lane & 3) * 2;
            *reinterpret_cast<float2*>(out + (size_t)row0 * ND + col) =
                make_float2(e[0], e[1]);
            *reinterpret_cast<float2*>(out + (size_t)(row0 + 8) * ND + col) =
                make_float2(e[2], e[3]);
        }
    }
}

// ---------------------------------------------------------------------------
extern "C" void kernel_launch(void* const* d_in, const int* in_sizes, int n_in,
                              void* d_out, int out_size)
{
    const float* A    = (const float*)d_in[0];   // [65536, 256]
    const float* W    = (const float*)d_in[1];   // [256, 256]
    const float* bias = (const float*)d_in[2];   // [8]
    float* out = (float*)d_out;

    convert_W<<<(ND * KD) / (4 * 256), 256>>>(W);

    cudaFuncSetAttribute(bc_mma, cudaFuncAttributeMaxDynamicSharedMemorySize,
                         SMEM_TOTAL);
    bc_mma<<<MROWS / BM, THREADS, SMEM_TOTAL>>>(A, bias, out);
    (void)in_sizes; (void)n_in; (void)out_size;
}

// round 7
// speedup vs baseline: 4.2942x; 1.0099x over previous
#include <cuda_runtime.h>
#include <cuda_fp16.h>
#include <cuda_pipeline.h>
#include <cstdint>

// ============================================================================
// BlockConvolutionLean, fp16 mma.sync, occupancy-optimized (2 CTAs/SM):
//   out = segmented-exclusive-cumsum_8( A @ W^T ) + b_eff, b_eff[0]=2*bias[0]
// Pass 1: A fp32 -> fp16 (96MB traffic; result L2-resident for pass 2).
// Pass 2: GEMM, BM=128 x BN=128 per 256-thread CTA, pure cp.async fills
//   (no LDG/cvt/STS in mainloop), 3-stage pipeline, <=128 regs -> 2 CTAs/SM.
// ============================================================================

#define MROWS 65536
#define KD 256
#define ND 256
#define BM 128
#define BN 128
#define THREADS 256
#define NCH 4                          // K chunks of 64

// Per stage: W 16KB + A 16KB. 3 stages = 96KB.
#define STAGE_BYTES 32768
#define OFF_WS 0
#define OFF_AS 16384
#define SMEM_TOTAL (3 * STAGE_BYTES)

__device__ __half g_Whf[ND * KD];               // W fp16
__device__ __half g_Ahf[(size_t)MROWS * KD];    // A fp16 (32 MB scratch)

// ---------------------------------------------------------------------------
__device__ __forceinline__ uint32_t smem_u32(const void* p) {
    uint32_t a;
    asm("{ .reg .u64 t; cvta.to.shared.u64 t, %1; cvt.u32.u64 %0, t; }"
        : "=r"(a) : "l"(p));
    return a;
}
__device__ __forceinline__ void ldsm_x4(uint32_t* r, uint32_t addr) {
    asm volatile("ldmatrix.sync.aligned.m8n8.x4.shared.b16 {%0,%1,%2,%3}, [%4];"
                 : "=r"(r[0]), "=r"(r[1]), "=r"(r[2]), "=r"(r[3]) : "r"(addr));
}
__device__ __forceinline__ void mma_f16(float* c, const uint32_t* a, const uint32_t* b) {
    asm volatile("mma.sync.aligned.m16n8k16.row.col.f32.f16.f16.f32 "
                 "{%0,%1,%2,%3}, {%4,%5,%6,%7}, {%8,%9}, {%0,%1,%2,%3};"
                 : "+f"(c[0]), "+f"(c[1]), "+f"(c[2]), "+f"(c[3])
                 : "r"(a[0]), "r"(a[1]), "r"(a[2]), "r"(a[3]), "r"(b[0]), "r"(b[1]));
}

// ---------------------------------------------------------------------------
__global__ __launch_bounds__(256) void convert_W(const float* __restrict__ W) {
    int i = (blockIdx.x * 256 + threadIdx.x) * 4;
    float4 v = *reinterpret_cast<const float4*>(W + i);
    __half2 h0 = __floats2half2_rn(v.x, v.y);
    __half2 h1 = __floats2half2_rn(v.z, v.w);
    uint2 u = { *reinterpret_cast<uint32_t*>(&h0), *reinterpret_cast<uint32_t*>(&h1) };
    *reinterpret_cast<uint2*>(g_Whf + i) = u;
}

__global__ __launch_bounds__(256) void convert_A(const float* __restrict__ A) {
    size_t i = ((size_t)blockIdx.x * 256 + threadIdx.x) * 8;
    float4 v0 = *reinterpret_cast<const float4*>(A + i);
    float4 v1 = *reinterpret_cast<const float4*>(A + i + 4);
    __half2 h0 = __floats2half2_rn(v0.x, v0.y);
    __half2 h1 = __floats2half2_rn(v0.z, v0.w);
    __half2 h2 = __floats2half2_rn(v1.x, v1.y);
    __half2 h3 = __floats2half2_rn(v1.z, v1.w);
    uint4 u = { *reinterpret_cast<uint32_t*>(&h0), *reinterpret_cast<uint32_t*>(&h1),
                *reinterpret_cast<uint32_t*>(&h2), *reinterpret_cast<uint32_t*>(&h3) };
    *reinterpret_cast<uint4*>(g_Ahf + i) = u;
}

// ---------------------------------------------------------------------------
// Fill one pipeline stage (W tile rows n0.., A tile rows m0.., K chunk c).
// 128 rows x 8 x 16B each => 4 cp.async per thread per matrix.
__device__ __forceinline__ void fill_stage(char* smem, int st, int c,
                                           int m0, int n0, int tid) {
    char* base = smem + st * STAGE_BYTES;
    const int k0 = c * 64;
#pragma unroll
    for (int i = 0; i < 4; i++) {
        int v = tid + i * THREADS;         // 0..1023
        int row = v >> 3, seg = v & 7;
        uint32_t off = (uint32_t)row * 128 + (uint32_t)((seg * 16) ^ ((row & 7) << 4));
        __pipeline_memcpy_async(base + OFF_WS + off,
                                g_Whf + (size_t)(n0 + row) * KD + k0 + seg * 8, 16);
        __pipeline_memcpy_async(base + OFF_AS + off,
                                g_Ahf + (size_t)(m0 + row) * KD + k0 + seg * 8, 16);
    }
}

// ---------------------------------------------------------------------------
__global__ __launch_bounds__(THREADS, 2)
void bc_mma(const float* __restrict__ bias, float* __restrict__ out)
{
    extern __shared__ __align__(1024) char smem[];
    const int tid = threadIdx.x;
    const int lane = tid & 31, w = tid >> 5;
    const int wm = w >> 2, wn = w & 3;         // 2(m) x 4(n); warp tile 64 x 32
    const int n0 = blockIdx.x * BN;            // fast dim (2) -> A L2 reuse
    const int m0 = blockIdx.y * BM;

    // Prologue: stages 0,1 <- chunks 0,1
    fill_stage(smem, 0, 0, m0, n0, tid); __pipeline_commit();
    fill_stage(smem, 1, 1, m0, n0, tid); __pipeline_commit();

    float acc[4][4][4] = {};

    const uint32_t sb = smem_u32(smem);
    const uint32_t xorv   = (uint32_t)(lane & 7) << 4;
    const uint32_t a_row  = (uint32_t)(wm * 64 + (lane & 15));
    const uint32_t a_csel = ((uint32_t)(lane >> 4)) << 4;
    const uint32_t b_row  = (uint32_t)(wn * 32 + ((lane >> 4) << 3) + (lane & 7));
    const uint32_t b_csel = ((uint32_t)((lane >> 3) & 1)) << 4;

    __pipeline_wait_prior(1);                  // chunk 0 ready
    __syncthreads();

#pragma unroll
    for (int c = 0; c < NCH; c++) {
        if (c + 2 < NCH) {
            // stage (c+2)%3 was last read in chunk c-1 (guarded by its sync)
            fill_stage(smem, (c + 2) % 3, c + 2, m0, n0, tid);
            __pipeline_commit();
        }

        const uint32_t stb = sb + (uint32_t)(c % 3) * STAGE_BYTES;
#pragma unroll
        for (int s = 0; s < 4; s++) {
            const uint32_t ksa = (((uint32_t)s * 32) + a_csel) ^ xorv;
            const uint32_t ksb = (((uint32_t)s * 32) + b_csel) ^ xorv;
            uint32_t a[4][4], b[2][4];
#pragma unroll
            for (int mf = 0; mf < 4; mf++)
                ldsm_x4(a[mf], stb + OFF_AS + (a_row + mf * 16) * 128 + ksa);
#pragma unroll
            for (int nfp = 0; nfp < 2; nfp++)
                ldsm_x4(b[nfp], stb + OFF_WS + (b_row + nfp * 16) * 128 + ksb);
#pragma unroll
            for (int mf = 0; mf < 4; mf++)
#pragma unroll
                for (int nfp = 0; nfp < 2; nfp++) {
                    mma_f16(acc[mf][2 * nfp],     a[mf], b[nfp]);
                    mma_f16(acc[mf][2 * nfp + 1], a[mf], b[nfp] + 2);
                }
        }

        if (c + 1 < NCH) {
            // ensure chunk c+1's cp.async group has landed, then barrier so
            // (a) everyone sees it, (b) stage reuse above is safe next iter.
            __pipeline_wait_prior((c + 2 < NCH) ? 1 : 0);
            __syncthreads();
        }
    }

    // ---- epilogue: segmented exclusive scan over 8-row blocks + bias ----
    const int p = lane >> 2;                   // block position 0..7
    float be = __ldg(bias + p);
    if (p == 0) be += be;                      // b_eff[0] = 2*bias[0]

#pragma unroll
    for (int mf = 0; mf < 4; mf++) {
#pragma unroll
        for (int nf = 0; nf < 4; nf++) {
            float e[4];
#pragma unroll
            for (int q = 0; q < 4; q++) {
                float v = acc[mf][nf][q];
                float sgm = v, t;
                t = __shfl_up_sync(0xffffffffu, sgm, 4);  if (p >= 1) sgm += t;
                t = __shfl_up_sync(0xffffffffu, sgm, 8);  if (p >= 2) sgm += t;
                t = __shfl_up_sync(0xffffffffu, sgm, 16); if (p >= 4) sgm += t;
                e[q] = sgm - v + be;
            }
            const int row0 = m0 + wm * 64 + mf * 16 + p;
            const int col  = n0 + wn * 32 + nf * 8 + (lane & 3) * 2;
            *reinterpret_cast<float2*>(out + (size_t)row0 * ND + col) =
                make_float2(e[0], e[1]);
            *reinterpret_cast<float2*>(out + (size_t)(row0 + 8) * ND + col) =
                make_float2(e[2], e[3]);
        }
    }
}

// ---------------------------------------------------------------------------
extern "C" void kernel_launch(void* const* d_in, const int* in_sizes, int n_in,
                              void* d_out, int out_size)
{
    const float* A    = (const float*)d_in[0];   // [65536, 256]
    const float* W    = (const float*)d_in[1];   // [256, 256]
    const float* bias = (const float*)d_in[2];   // [8]
    float* out = (float*)d_out;

    convert_W<<<(ND * KD) / (4 * 256), 256>>>(W);
    convert_A<<<(int)(((size_t)MROWS * KD) / (8 * 256)), 256>>>(A);

    cudaFuncSetAttribute(bc_mma, cudaFuncAttributeMaxDynamicSharedMemorySize,
                         SMEM_TOTAL);
    dim3 grid(ND / BN, MROWS / BM);              // (2, 512)
    bc_mma<<<grid, THREADS, SMEM_TOTAL>>>(bias, out);
    (void)in_sizes; (void)n_in; (void)out_size;
}

// round 8
// speedup vs baseline: 4.9435x; 1.1512x over previous
#include <cuda_runtime.h>
#include <cuda_fp16.h>
#include <cuda_pipeline.h>
#include <cstdint>

// ============================================================================
// BlockConvolutionLean, fp16 mma.sync, fused A-conversion + 2 CTAs/SM:
//   out = segmented-exclusive-cumsum_8( A @ W^T ) + b_eff, b_eff[0]=2*bias[0]
// - W fp16 (pre-converted micro-kernel), CTA's 128xK tile smem-resident.
// - A: full-line LDG.128 -> cvt f16x2 (held as 16 regs) -> swizzled STS ->
//   ldmatrix; 2-stage buffer; LDG/cvt/STS interleaved with k-steps.
// - BN=128 => acc 64 regs/thread => 2 CTAs/SM (16 warps).
// ============================================================================

#define MROWS 65536
#define KD 256
#define ND 256
#define BM 128
#define BN 128
#define THREADS 256
#define NCH 4                          // K chunks of 64

#define W_REGION 16384                 // 128 rows x 128B (one K=64 chunk)
#define OFF_A (4 * W_REGION)           // 65536: W resident (4 regions)
#define A_STAGE 16384                  // 128 rows x 128B
#define SMEM_TOTAL (OFF_A + 2 * A_STAGE)   // 98304 B -> 2 CTAs = 192KB

__device__ __half g_Whf[ND * KD];      // W fp16

// ---------------------------------------------------------------------------
__device__ __forceinline__ uint32_t smem_u32(const void* p) {
    uint32_t a;
    asm("{ .reg .u64 t; cvta.to.shared.u64 t, %1; cvt.u32.u64 %0, t; }"
        : "=r"(a) : "l"(p));
    return a;
}
__device__ __forceinline__ void ldsm_x4(uint32_t* r, uint32_t addr) {
    asm volatile("ldmatrix.sync.aligned.m8n8.x4.shared.b16 {%0,%1,%2,%3}, [%4];"
                 : "=r"(r[0]), "=r"(r[1]), "=r"(r[2]), "=r"(r[3]) : "r"(addr));
}
__device__ __forceinline__ void mma_f16(float* c, const uint32_t* a, const uint32_t* b) {
    asm volatile("mma.sync.aligned.m16n8k16.row.col.f32.f16.f16.f32 "
                 "{%0,%1,%2,%3}, {%4,%5,%6,%7}, {%8,%9}, {%0,%1,%2,%3};"
                 : "+f"(c[0]), "+f"(c[1]), "+f"(c[2]), "+f"(c[3])
                 : "r"(a[0]), "r"(a[1]), "r"(a[2]), "r"(a[3]), "r"(b[0]), "r"(b[1]));
}
__device__ __forceinline__ uint32_t h2u(__half2 h) {
    return *reinterpret_cast<uint32_t*>(&h);
}
__device__ __forceinline__ uint2 cvt2(float4 v) {
    __half2 h0 = __floats2half2_rn(v.x, v.y);
    __half2 h1 = __floats2half2_rn(v.z, v.w);
    return make_uint2(h2u(h0), h2u(h1));
}

// ---------------------------------------------------------------------------
__global__ __launch_bounds__(256) void convert_W(const float* __restrict__ W) {
    int i = (blockIdx.x * 256 + threadIdx.x) * 4;
    float4 v = *reinterpret_cast<const float4*>(W + i);
    uint2 u = cvt2(v);
    *reinterpret_cast<uint2*>(g_Whf + i) = u;
}

// ---------------------------------------------------------------------------
__global__ __launch_bounds__(THREADS, 2)
void bc_mma(const float* __restrict__ A, const float* __restrict__ bias,
            float* __restrict__ out)
{
    extern __shared__ __align__(1024) char smem[];
    const int tid = threadIdx.x;
    const int lane = tid & 31, w = tid >> 5;
    const int wm = w >> 2, wn = w & 3;         // 2(m) x 4(n); warp tile 64 x 32
    const int n0 = blockIdx.x * BN;            // fast dim (2) -> A L2 reuse
    const int m0 = blockIdx.y * BM;

    // ---- prologue: W tile (128 x K=256 fp16, 4 swizzled regions) ----
#pragma unroll
    for (int i = 0; i < 16; i++) {
        int v = tid + i * THREADS;             // 0..4095
        int c = v >> 10;                       // region 0..3
        int r = (v >> 3) & 127;                // W row 0..127
        int seg = v & 7;
        uint32_t off = (uint32_t)c * W_REGION + (uint32_t)r * 128 +
                       (uint32_t)((seg * 16) ^ ((r & 7) << 4));
        __pipeline_memcpy_async(smem + off,
                                g_Whf + (size_t)(n0 + r) * KD + c * 64 + seg * 8, 16);
    }
    __pipeline_commit();

    // ---- A chunk 0: LDG full-line -> cvt -> STS stage 0 ----
    // warp covers rows w*16..+15; instr j covers rows (2j, 2j+1).
    const int rbase = w * 16 + (lane >> 4);
    const float* ag = A + (size_t)(m0 + rbase) * KD + (lane & 15) * 4;
    const uint32_t stscol = (uint32_t)(lane & 15) * 8;

    {
        uint2 pc[8];
#pragma unroll
        for (int j = 0; j < 8; j++)
            pc[j] = cvt2(*reinterpret_cast<const float4*>(ag + j * 2 * KD));
#pragma unroll
        for (int j = 0; j < 8; j++) {
            int row = rbase + 2 * j;
            uint32_t off = (uint32_t)row * 128 + (stscol ^ (uint32_t)((row & 7) << 4));
            *reinterpret_cast<uint2*>(smem + OFF_A + off) = pc[j];
        }
    }

    float acc[4][4][4] = {};

    const uint32_t sb = smem_u32(smem);
    const uint32_t xorv   = (uint32_t)(lane & 7) << 4;
    const uint32_t a_row  = (uint32_t)(wm * 64 + (lane & 15));
    const uint32_t a_csel = ((uint32_t)(lane >> 4)) << 4;
    const uint32_t b_row  = (uint32_t)(wn * 32 + ((lane >> 4) << 3) + (lane & 7));
    const uint32_t b_csel = ((uint32_t)((lane >> 3) & 1)) << 4;

    __pipeline_wait_prior(0);
    __syncthreads();

    // ---- mainloop: 4 chunks x 4 k-steps, 2-stage A, 1 sync per chunk ----
#pragma unroll
    for (int c = 0; c < NCH; c++) {
        const uint32_t abase = sb + OFF_A + (uint32_t)(c & 1) * A_STAGE;
        const uint32_t wbase = sb + (uint32_t)c * W_REGION;
        char* nstage = smem + OFF_A + ((c + 1) & 1) * A_STAGE;

        float4 pf[4];
        if (c < NCH - 1) {
#pragma unroll
            for (int j = 0; j < 4; j++)
                pf[j] = *reinterpret_cast<const float4*>(
                    ag + (c + 1) * 64 + j * 2 * KD);
        }

#pragma unroll
        for (int s = 0; s < 2; s++) {
            const uint32_t ksa = (((uint32_t)s * 32) + a_csel) ^ xorv;
            const uint32_t ksb = (((uint32_t)s * 32) + b_csel) ^ xorv;
            uint32_t a[4][4], b[2][4];
#pragma unroll
            for (int mf = 0; mf < 4; mf++)
                ldsm_x4(a[mf], abase + (a_row + mf * 16) * 128 + ksa);
#pragma unroll
            for (int nfp = 0; nfp < 2; nfp++)
                ldsm_x4(b[nfp], wbase + (b_row + nfp * 16) * 128 + ksb);
#pragma unroll
            for (int mf = 0; mf < 4; mf++)
#pragma unroll
                for (int nfp = 0; nfp < 2; nfp++) {
                    mma_f16(acc[mf][2 * nfp],     a[mf], b[nfp]);
                    mma_f16(acc[mf][2 * nfp + 1], a[mf], b[nfp] + 2);
                }
        }

        if (c < NCH - 1) {
#pragma unroll
            for (int j = 0; j < 4; j++) {
                int row = rbase + 2 * j;
                uint32_t off = (uint32_t)row * 128 +
                               (stscol ^ (uint32_t)((row & 7) << 4));
                *reinterpret_cast<uint2*>(nstage + off) = cvt2(pf[j]);
            }
#pragma unroll
            for (int j = 0; j < 4; j++)
                pf[j] = *reinterpret_cast<const float4*>(
                    ag + (c + 1) * 64 + (4 + j) * 2 * KD);
        }

#pragma unroll
        for (int s = 2; s < 4; s++) {
            const uint32_t ksa = (((uint32_t)s * 32) + a_csel) ^ xorv;
            const uint32_t ksb = (((uint32_t)s * 32) + b_csel) ^ xorv;
            uint32_t a[4][4], b[2][4];
#pragma unroll
            for (int mf = 0; mf < 4; mf++)
                ldsm_x4(a[mf], abase + (a_row + mf * 16) * 128 + ksa);
#pragma unroll
            for (int nfp = 0; nfp < 2; nfp++)
                ldsm_x4(b[nfp], wbase + (b_row + nfp * 16) * 128 + ksb);
#pragma unroll
            for (int mf = 0; mf < 4; mf++)
#pragma unroll
                for (int nfp = 0; nfp < 2; nfp++) {
                    mma_f16(acc[mf][2 * nfp],     a[mf], b[nfp]);
                    mma_f16(acc[mf][2 * nfp + 1], a[mf], b[nfp] + 2);
                }
        }

        if (c < NCH - 1) {
#pragma unroll
            for (int j = 0; j < 4; j++) {
                int row = rbase + 2 * (4 + j);
                uint32_t off = (uint32_t)row * 128 +
                               (stscol ^ (uint32_t)((row & 7) << 4));
                *reinterpret_cast<uint2*>(nstage + off) = cvt2(pf[j]);
            }
            __syncthreads();
        }
    }

    // ---- epilogue: segmented exclusive scan over 8-row blocks + bias ----
    const int p = lane >> 2;                   // block position 0..7
    float be = __ldg(bias + p);
    if (p == 0) be += be;                      // b_eff[0] = 2*bias[0]

#pragma unroll
    for (int mf = 0; mf < 4; mf++) {
#pragma unroll
        for (int nf = 0; nf < 4; nf++) {
            float e[4];
#pragma unroll
            for (int q = 0; q < 4; q++) {
                float v = acc[mf][nf][q];
                float sgm = v, t;
                t = __shfl_up_sync(0xffffffffu, sgm, 4);  if (p >= 1) sgm += t;
                t = __shfl_up_sync(0xffffffffu, sgm, 8);  if (p >= 2) sgm += t;
                t = __shfl_up_sync(0xffffffffu, sgm, 16); if (p >= 4) sgm += t;
                e[q] = sgm - v + be;
            }
            const int row0 = m0 + wm * 64 + mf * 16 + p;
            const int col  = n0 + wn * 32 + nf * 8 + (lane & 3) * 2;
            *reinterpret_cast<float2*>(out + (size_t)row0 * ND + col) =
                make_float2(e[0], e[1]);
            *reinterpret_cast<float2*>(out + (size_t)(row0 + 8) * ND + col) =
                make_float2(e[2], e[3]);
        }
    }
}

// ---------------------------------------------------------------------------
extern "C" void kernel_launch(void* const* d_in, const int* in_sizes, int n_in,
                              void* d_out, int out_size)
{
    const float* A    = (const float*)d_in[0];   // [65536, 256]
    const float* W    = (const float*)d_in[1];   // [256, 256]
    const float* bias = (const float*)d_in[2];   // [8]
    float* out = (float*)d_out;

    convert_W<<<(ND * KD) / (4 * 256), 256>>>(W);

    cudaFuncSetAttribute(bc_mma, cudaFuncAttributeMaxDynamicSharedMemorySize,
                         SMEM_TOTAL);
    dim3 grid(ND / BN, MROWS / BM);              // (2, 512)
    bc_mma<<<grid, THREADS, SMEM_TOTAL>>>(A, bias, out);
    (void)in_sizes; (void)n_in; (void)out_size;
}